// round 4
// baseline (speedup 1.0000x reference)
#include <cuda_runtime.h>

#define N_B   4
#define C_CH  256
#define HW    4096
#define NH    4
#define DH    64
#define NPIX  (C_CH * HW)   // 1048576 elements per sample

// ---------------- scratch (static device globals; no allocs) ----------------
__device__ float g_part[N_B][128][2];
__device__ float g_stats[N_B][2];                       // mean, inv_std
__device__ float g_qkv[(size_t)N_B * 3 * C_CH * HW];    // [n][768][4096]
__device__ float g_y[(size_t)N_B * C_CH * HW];          // [n][256][4096]

// ---------------- GroupNorm stats: pass 1 ----------------
__global__ __launch_bounds__(256) void k_stat1(const float* __restrict__ x) {
    int n = blockIdx.y, part = blockIdx.x, tid = threadIdx.x;
    const float* p = x + (size_t)n * NPIX + (size_t)part * 8192;
    float s = 0.f, q = 0.f;
#pragma unroll
    for (int i = 0; i < 32; i++) { float v = p[i * 256 + tid]; s += v; q += v * v; }
    __shared__ float ss[256], sq[256];
    ss[tid] = s; sq[tid] = q;
    __syncthreads();
    for (int o = 128; o > 0; o >>= 1) {
        if (tid < o) { ss[tid] += ss[tid + o]; sq[tid] += sq[tid + o]; }
        __syncthreads();
    }
    if (tid == 0) { g_part[n][part][0] = ss[0]; g_part[n][part][1] = sq[0]; }
}

// ---------------- GroupNorm stats: pass 2 ----------------
__global__ __launch_bounds__(128) void k_stat2() {
    int n = blockIdx.x, tid = threadIdx.x;
    __shared__ float ss[128], sq[128];
    ss[tid] = g_part[n][tid][0]; sq[tid] = g_part[n][tid][1];
    __syncthreads();
    for (int o = 64; o > 0; o >>= 1) {
        if (tid < o) { ss[tid] += ss[tid + o]; sq[tid] += sq[tid + o]; }
        __syncthreads();
    }
    if (tid == 0) {
        float mean = ss[0] / (float)NPIX;
        float var  = sq[0] / (float)NPIX - mean * mean;
        g_stats[n][0] = mean;
        g_stats[n][1] = rsqrtf(var + 1e-5f);
    }
}

// ---------------- QKV GEMM with fused GroupNorm ----------------
__global__ __launch_bounds__(256) void k_qkv(const float* __restrict__ x,
                                             const float* __restrict__ gamma,
                                             const float* __restrict__ beta,
                                             const float* __restrict__ w,
                                             const float* __restrict__ bias) {
    __shared__ float As[64][20];
    __shared__ float Bs[16][68];
    int n = blockIdx.z, o0 = blockIdx.y * 64, p0 = blockIdx.x * 64;
    int tid = threadIdx.x, tx = tid & 15, ty = tid >> 4;
    float mean = g_stats[n][0], inv = g_stats[n][1];
    float acc[4][4] = {};
    int ar = tid >> 2, ac = (tid & 3) << 2;
    int br = tid >> 4, bc = (tid & 15) << 2;
    for (int k0 = 0; k0 < C_CH; k0 += 16) {
        *(float4*)&As[ar][ac] = *(const float4*)&w[(size_t)(o0 + ar) * C_CH + k0 + ac];
        float g  = gamma[k0 + br] * inv;
        float bb = beta[k0 + br] - mean * g;
        float4 bv = *(const float4*)&x[((size_t)n * C_CH + k0 + br) * HW + p0 + bc];
        bv.x = bv.x * g + bb; bv.y = bv.y * g + bb; bv.z = bv.z * g + bb; bv.w = bv.w * g + bb;
        *(float4*)&Bs[br][bc] = bv;
        __syncthreads();
#pragma unroll
        for (int kk = 0; kk < 16; kk++) {
            float av[4];
#pragma unroll
            for (int i = 0; i < 4; i++) av[i] = As[ty * 4 + i][kk];
            float4 b4 = *(const float4*)&Bs[kk][tx << 2];
            float bvv[4] = {b4.x, b4.y, b4.z, b4.w};
#pragma unroll
            for (int i = 0; i < 4; i++)
#pragma unroll
                for (int j = 0; j < 4; j++) acc[i][j] += av[i] * bvv[j];
        }
        __syncthreads();
    }
    float* dst = g_qkv + ((size_t)n * 768 + o0) * HW + p0;
#pragma unroll
    for (int i = 0; i < 4; i++) {
        int o = ty * 4 + i;
        float bi = bias[o0 + o];
        float4 r = make_float4(acc[i][0] + bi, acc[i][1] + bi, acc[i][2] + bi, acc[i][3] + bi);
        *(float4*)&dst[(size_t)o * HW + (tx << 2)] = r;
    }
}

// ---------------- tf32 mma helpers ----------------
__device__ __forceinline__ unsigned f2tf(float f) {
    unsigned u;
    asm("cvt.rna.tf32.f32 %0, %1;" : "=r"(u) : "f"(f));
    return u;
}
__device__ __forceinline__ void mma_tf32(float c[4], const unsigned a[4],
                                         unsigned b0, unsigned b1) {
    asm volatile(
        "mma.sync.aligned.m16n8k8.row.col.f32.tf32.tf32.f32 "
        "{%0,%1,%2,%3}, {%4,%5,%6,%7}, {%8,%9}, {%0,%1,%2,%3};"
        : "+f"(c[0]), "+f"(c[1]), "+f"(c[2]), "+f"(c[3])
        : "r"(a[0]), "r"(a[1]), "r"(a[2]), "r"(a[3]), "r"(b0), "r"(b1));
}

// ---------------- flash attention via tf32 tensor cores ----------------
// S = Q^T K (M=64 q, N=64 k, Kdim=64 d), online softmax, O = P V.
// 8 warps: warp = qg*2 + ch; qg -> 16 q-rows, ch -> 32-col half.
#define KP 72   // Ks pitch (B-frag QK loads: bank = 8*tq + tg, conflict-free)
#define VP 68   // Vs pitch (B-frag PV loads: bank = 4*tg + tq, conflict-free)
#define PP 68   // Ps pitch (A-frag loads:    bank = 4*tg + tq, conflict-free)
#define ATT2_SMEM_FLOATS (64*KP + 64*VP + 64*PP + 64 + 64 + 128 + 128)
#define ATT2_SMEM_BYTES  (ATT2_SMEM_FLOATS * 4)

__global__ __launch_bounds__(256) void k_att() {
    extern __shared__ float sm[];
    float* Ks   = sm;                 // [d][pk]  pitch KP
    float* Vs   = Ks + 64 * KP;       // [d][pk]  pitch VP
    float* Ps   = Vs + 64 * VP;       // [q][*]   pitch PP (Q staging, then P)
    float* m_s  = Ps + 64 * PP;
    float* l_s  = m_s + 64;
    float* redm = l_s + 64;           // [2][64]
    float* redl = redm + 128;         // [2][64]

    int q0 = blockIdx.x * 64, head = blockIdx.y, n = blockIdx.z;
    int tid = threadIdx.x;
    int warp = tid >> 5, lane = tid & 31;
    int qg = warp >> 1, ch = warp & 1;
    int tg = lane >> 2, tq = lane & 3;
    int r0 = qg * 16 + tg;            // local q row (and +8)

    const float* qp = g_qkv + ((size_t)n * 768 + (head)          * 64) * HW;
    const float* kp = g_qkv + ((size_t)n * 768 + (NH + head)     * 64) * HW;
    const float* vp = g_qkv + ((size_t)n * 768 + (2 * NH + head) * 64) * HW;

    // stage Q to Ps transposed: Ps[q][d]
    int lr = tid >> 4;                // 0..15
    int lc4 = (tid & 15) << 2;        // 0..60 step 4
#pragma unroll
    for (int rr = 0; rr < 4; rr++) {
        int d = lr + rr * 16;
        float4 v = *(const float4*)&qp[(size_t)d * HW + q0 + lc4];
        Ps[(lc4 + 0) * PP + d] = v.x;
        Ps[(lc4 + 1) * PP + d] = v.y;
        Ps[(lc4 + 2) * PP + d] = v.z;
        Ps[(lc4 + 3) * PP + d] = v.w;
    }
    if (tid < 64) { m_s[tid] = -1e30f; l_s[tid] = 0.f; }
    __syncthreads();

    // Q A-fragments resident, pre-scaled by 1/8 (= dh^-0.5)
    unsigned a[8][4];
#pragma unroll
    for (int kf = 0; kf < 8; kf++) {
        int d0 = kf * 8 + tq;
        a[kf][0] = f2tf(0.125f * Ps[r0 * PP + d0]);
        a[kf][1] = f2tf(0.125f * Ps[(r0 + 8) * PP + d0]);
        a[kf][2] = f2tf(0.125f * Ps[r0 * PP + d0 + 4]);
        a[kf][3] = f2tf(0.125f * Ps[(r0 + 8) * PP + d0 + 4]);
    }

    float o[4][4] = {};

    for (int kt = 0; kt < 64; kt++) {
        int k0 = kt * 64;
        __syncthreads();   // prior PV / P reads done; Ks/Vs/Ps reusable
#pragma unroll
        for (int rr = 0; rr < 4; rr++) {
            int d = lr + rr * 16;
            *(float4*)&Ks[d * KP + lc4] = *(const float4*)&kp[(size_t)d * HW + k0 + lc4];
            *(float4*)&Vs[d * VP + lc4] = *(const float4*)&vp[(size_t)d * HW + k0 + lc4];
        }
        __syncthreads();   // tiles ready

        // ---- S = (Q/8)^T K  via tf32 mma
        float sf[4][4] = {};
#pragma unroll
        for (int kf = 0; kf < 8; kf++) {
            int krow = kf * 8 + tq;
#pragma unroll
            for (int nf = 0; nf < 4; nf++) {
                int ncol = ch * 32 + nf * 8 + tg;
                unsigned b0 = f2tf(Ks[krow * KP + ncol]);
                unsigned b1 = f2tf(Ks[(krow + 4) * KP + ncol]);
                mma_tf32(sf[nf], a[kf], b0, b1);
            }
        }

        // ---- row max (rows r0, r0+8), quad shuffle + 2-warp combine
        float mx0 = -1e30f, mx1 = -1e30f;
#pragma unroll
        for (int nf = 0; nf < 4; nf++) {
            mx0 = fmaxf(mx0, fmaxf(sf[nf][0], sf[nf][1]));
            mx1 = fmaxf(mx1, fmaxf(sf[nf][2], sf[nf][3]));
        }
        mx0 = fmaxf(mx0, __shfl_xor_sync(0xffffffffu, mx0, 1));
        mx0 = fmaxf(mx0, __shfl_xor_sync(0xffffffffu, mx0, 2));
        mx1 = fmaxf(mx1, __shfl_xor_sync(0xffffffffu, mx1, 1));
        mx1 = fmaxf(mx1, __shfl_xor_sync(0xffffffffu, mx1, 2));
        redm[ch * 64 + r0]     = mx0;
        redm[ch * 64 + r0 + 8] = mx1;
        __syncthreads();   // redm published

        float mt0 = fmaxf(redm[r0],     redm[64 + r0]);
        float mt1 = fmaxf(redm[r0 + 8], redm[64 + r0 + 8]);
        float mo0 = m_s[r0], mo1 = m_s[r0 + 8];
        float mn0 = fmaxf(mo0, mt0), mn1 = fmaxf(mo1, mt1);
        float al0 = __expf(mo0 - mn0), al1 = __expf(mo1 - mn1);

        float sum0 = 0.f, sum1 = 0.f;
#pragma unroll
        for (int nf = 0; nf < 4; nf++) {
            float p0 = __expf(sf[nf][0] - mn0);
            float p1 = __expf(sf[nf][1] - mn0);
            float p2 = __expf(sf[nf][2] - mn1);
            float p3 = __expf(sf[nf][3] - mn1);
            sum0 += p0 + p1; sum1 += p2 + p3;
            int col = ch * 32 + nf * 8 + 2 * tq;
            *(float2*)&Ps[r0 * PP + col] =
                make_float2(__uint_as_float(f2tf(p0)), __uint_as_float(f2tf(p1)));
            *(float2*)&Ps[(r0 + 8) * PP + col] =
                make_float2(__uint_as_float(f2tf(p2)), __uint_as_float(f2tf(p3)));
        }
        sum0 += __shfl_xor_sync(0xffffffffu, sum0, 1);
        sum0 += __shfl_xor_sync(0xffffffffu, sum0, 2);
        sum1 += __shfl_xor_sync(0xffffffffu, sum1, 1);
        sum1 += __shfl_xor_sync(0xffffffffu, sum1, 2);
        redl[ch * 64 + r0]     = sum0;
        redl[ch * 64 + r0 + 8] = sum1;

        // rescale O
#pragma unroll
        for (int nf = 0; nf < 4; nf++) {
            o[nf][0] *= al0; o[nf][1] *= al0;
            o[nf][2] *= al1; o[nf][3] *= al1;
        }
        __syncthreads();   // P + redl published

        // single-writer stats update (safe: next read of m_s is after next 2 barriers)
        if (ch == 0 && tq == 0) {
            m_s[r0]     = mn0;
            m_s[r0 + 8] = mn1;
            l_s[r0]     = l_s[r0]     * al0 + redl[r0]     + redl[64 + r0];
            l_s[r0 + 8] = l_s[r0 + 8] * al1 + redl[r0 + 8] + redl[64 + r0 + 8];
        }

        // ---- O += P V  via tf32 mma (A from Ps already tf32)
#pragma unroll
        for (int kf = 0; kf < 8; kf++) {
            int pk = kf * 8 + tq;
            unsigned pa[4];
            pa[0] = __float_as_uint(Ps[r0 * PP + pk]);
            pa[1] = __float_as_uint(Ps[(r0 + 8) * PP + pk]);
            pa[2] = __float_as_uint(Ps[r0 * PP + pk + 4]);
            pa[3] = __float_as_uint(Ps[(r0 + 8) * PP + pk + 4]);
#pragma unroll
            for (int nf = 0; nf < 4; nf++) {
                int dv = ch * 32 + nf * 8 + tg;
                unsigned b0 = f2tf(Vs[dv * VP + pk]);
                unsigned b1 = f2tf(Vs[dv * VP + pk + 4]);
                mma_tf32(o[nf], pa, b0, b1);
            }
        }
    }

    __syncthreads();   // final l_s visible
    float linv0 = 1.f / l_s[r0];
    float linv1 = 1.f / l_s[r0 + 8];
    float* yp = g_y + ((size_t)n * C_CH + head * 64) * HW;
#pragma unroll
    for (int nf = 0; nf < 4; nf++) {
        int dv = ch * 32 + nf * 8 + 2 * tq;
        yp[(size_t)dv * HW + q0 + r0]           = o[nf][0] * linv0;
        yp[(size_t)(dv + 1) * HW + q0 + r0]     = o[nf][1] * linv0;
        yp[(size_t)dv * HW + q0 + r0 + 8]       = o[nf][2] * linv1;
        yp[(size_t)(dv + 1) * HW + q0 + r0 + 8] = o[nf][3] * linv1;
    }
}

// ---------------- out projection + bias + residual ----------------
__global__ __launch_bounds__(256) void k_out(const float* __restrict__ x,
                                             const float* __restrict__ w,
                                             const float* __restrict__ bias,
                                             float* __restrict__ out) {
    __shared__ float As[64][20];
    __shared__ float Bs[16][68];
    int n = blockIdx.z, o0 = blockIdx.y * 64, p0 = blockIdx.x * 64;
    int tid = threadIdx.x, tx = tid & 15, ty = tid >> 4;
    float acc[4][4] = {};
    int ar = tid >> 2, ac = (tid & 3) << 2;
    int br = tid >> 4, bc = (tid & 15) << 2;
    for (int k0 = 0; k0 < C_CH; k0 += 16) {
        *(float4*)&As[ar][ac] = *(const float4*)&w[(size_t)(o0 + ar) * C_CH + k0 + ac];
        *(float4*)&Bs[br][bc] =
            *(const float4*)&g_y[((size_t)n * C_CH + k0 + br) * HW + p0 + bc];
        __syncthreads();
#pragma unroll
        for (int kk = 0; kk < 16; kk++) {
            float av[4];
#pragma unroll
            for (int i = 0; i < 4; i++) av[i] = As[ty * 4 + i][kk];
            float4 b4 = *(const float4*)&Bs[kk][tx << 2];
            float bvv[4] = {b4.x, b4.y, b4.z, b4.w};
#pragma unroll
            for (int i = 0; i < 4; i++)
#pragma unroll
                for (int j = 0; j < 4; j++) acc[i][j] += av[i] * bvv[j];
        }
        __syncthreads();
    }
#pragma unroll
    for (int i = 0; i < 4; i++) {
        int o = o0 + ty * 4 + i;
        float bi = bias[o];
        size_t idx = ((size_t)n * C_CH + o) * HW + p0 + (tx << 2);
        float4 xr = *(const float4*)&x[idx];
        float4 r = make_float4(acc[i][0] + bi + xr.x, acc[i][1] + bi + xr.y,
                               acc[i][2] + bi + xr.z, acc[i][3] + bi + xr.w);
        *(float4*)&out[idx] = r;
    }
}

// ---------------- launch ----------------
extern "C" void kernel_launch(void* const* d_in, const int* in_sizes, int n_in,
                              void* d_out, int out_size) {
    (void)in_sizes; (void)n_in; (void)out_size;
    const float* x     = (const float*)d_in[0];
    const float* gamma = (const float*)d_in[1];
    const float* beta  = (const float*)d_in[2];
    const float* w_qkv = (const float*)d_in[3];
    const float* b_qkv = (const float*)d_in[4];
    const float* w_out = (const float*)d_in[5];
    const float* b_out = (const float*)d_in[6];
    float* out = (float*)d_out;

    cudaFuncSetAttribute(k_att, cudaFuncAttributeMaxDynamicSharedMemorySize, ATT2_SMEM_BYTES);

    k_stat1<<<dim3(128, N_B), 256>>>(x);
    k_stat2<<<N_B, 128>>>();
    k_qkv<<<dim3(HW / 64, 12, N_B), 256>>>(x, gamma, beta, w_qkv, b_qkv);
    k_att<<<dim3(HW / 64, NH, N_B), 256, ATT2_SMEM_BYTES>>>();
    k_out<<<dim3(HW / 64, 4, N_B), 256>>>(x, w_out, b_out, out);
}

// round 6
// speedup vs baseline: 1.8307x; 1.8307x over previous
#include <cuda_runtime.h>
#include <cuda_bf16.h>
#include <cstdint>

#define N_B   4
#define C_CH  256
#define HW    4096
#define NH    4
#define NPIX  (C_CH * HW)

__device__ float g_part[N_B][128][2];
__device__ float g_stats[N_B][2];
__device__ float g_qkv[(size_t)N_B * C_CH * HW];                 // Q fp32 [n][256][4096]
__device__ __nv_bfloat16 g_kbf[(size_t)N_B * HW * C_CH];         // K^T bf16 [n][4096][256]
__device__ __nv_bfloat16 g_vbf[(size_t)N_B * C_CH * HW];         // V bf16 [n][256][4096]
__device__ float g_y[(size_t)N_B * C_CH * HW];

// ---------------- GroupNorm stats ----------------
__global__ __launch_bounds__(256) void k_stat1(const float* __restrict__ x) {
    int n = blockIdx.y, part = blockIdx.x, tid = threadIdx.x;
    const float* p = x + (size_t)n * NPIX + (size_t)part * 8192;
    float s = 0.f, q = 0.f;
#pragma unroll
    for (int i = 0; i < 32; i++) { float v = p[i * 256 + tid]; s += v; q += v * v; }
    __shared__ float ss[256], sq[256];
    ss[tid] = s; sq[tid] = q;
    __syncthreads();
    for (int o = 128; o > 0; o >>= 1) {
        if (tid < o) { ss[tid] += ss[tid + o]; sq[tid] += sq[tid + o]; }
        __syncthreads();
    }
    if (tid == 0) { g_part[n][part][0] = ss[0]; g_part[n][part][1] = sq[0]; }
}

__global__ __launch_bounds__(128) void k_stat2() {
    int n = blockIdx.x, tid = threadIdx.x;
    __shared__ float ss[128], sq[128];
    ss[tid] = g_part[n][tid][0]; sq[tid] = g_part[n][tid][1];
    __syncthreads();
    for (int o = 64; o > 0; o >>= 1) {
        if (tid < o) { ss[tid] += ss[tid + o]; sq[tid] += sq[tid + o]; }
        __syncthreads();
    }
    if (tid == 0) {
        float mean = ss[0] / (float)NPIX;
        float var  = sq[0] / (float)NPIX - mean * mean;
        g_stats[n][0] = mean;
        g_stats[n][1] = rsqrtf(var + 1e-5f);
    }
}

// ---------------- QKV GEMM + GroupNorm; Q->fp32, K->bf16 transposed, V->bf16 ----------------
__global__ __launch_bounds__(256) void k_qkv(const float* __restrict__ x,
                                             const float* __restrict__ gamma,
                                             const float* __restrict__ beta,
                                             const float* __restrict__ w,
                                             const float* __restrict__ bias) {
    __shared__ float As[64][20];
    __shared__ float Bs[16][68];
    int n = blockIdx.z, o0 = blockIdx.y * 64, p0 = blockIdx.x * 64;
    int tid = threadIdx.x, tx = tid & 15, ty = tid >> 4;
    float mean = g_stats[n][0], inv = g_stats[n][1];
    float acc[4][4] = {};
    int ar = tid >> 2, ac = (tid & 3) << 2;
    int br = tid >> 4, bc = (tid & 15) << 2;
    for (int k0 = 0; k0 < C_CH; k0 += 16) {
        *(float4*)&As[ar][ac] = *(const float4*)&w[(size_t)(o0 + ar) * C_CH + k0 + ac];
        float g  = gamma[k0 + br] * inv;
        float bb = beta[k0 + br] - mean * g;
        float4 bv = *(const float4*)&x[((size_t)n * C_CH + k0 + br) * HW + p0 + bc];
        bv.x = bv.x * g + bb; bv.y = bv.y * g + bb; bv.z = bv.z * g + bb; bv.w = bv.w * g + bb;
        *(float4*)&Bs[br][bc] = bv;
        __syncthreads();
#pragma unroll
        for (int kk = 0; kk < 16; kk++) {
            float av[4];
#pragma unroll
            for (int i = 0; i < 4; i++) av[i] = As[ty * 4 + i][kk];
            float4 b4 = *(const float4*)&Bs[kk][tx << 2];
            float bvv[4] = {b4.x, b4.y, b4.z, b4.w};
#pragma unroll
            for (int i = 0; i < 4; i++)
#pragma unroll
                for (int j = 0; j < 4; j++) acc[i][j] += av[i] * bvv[j];
        }
        __syncthreads();
    }
    if (o0 < 256) {          // Q: fp32
        float* dst = g_qkv + ((size_t)n * 256 + o0) * HW + p0;
#pragma unroll
        for (int i = 0; i < 4; i++) {
            int o = ty * 4 + i;
            float bi = bias[o0 + o];
            float4 r = make_float4(acc[i][0]+bi, acc[i][1]+bi, acc[i][2]+bi, acc[i][3]+bi);
            *(float4*)&dst[(size_t)o * HW + (tx << 2)] = r;
        }
    } else if (o0 < 512) {   // K: bf16 transposed [pix][c]
#pragma unroll
        for (int i = 0; i < 4; i++) {
            int c = o0 - 256 + ty * 4 + i;
            float bi = bias[o0 + ty * 4 + i];
#pragma unroll
            for (int j = 0; j < 4; j++)
                g_kbf[((size_t)n * HW + p0 + tx * 4 + j) * 256 + c] =
                    __float2bfloat16(acc[i][j] + bi);
        }
    } else {                 // V: bf16 natural [c][pix]
#pragma unroll
        for (int i = 0; i < 4; i++) {
            int c = o0 - 512 + ty * 4 + i;
            float bi = bias[o0 + ty * 4 + i];
            __nv_bfloat162* bp = (__nv_bfloat162*)
                (g_vbf + ((size_t)n * 256 + c) * HW + p0 + tx * 4);
            bp[0] = __floats2bfloat162_rn(acc[i][0] + bi, acc[i][1] + bi);
            bp[1] = __floats2bfloat162_rn(acc[i][2] + bi, acc[i][3] + bi);
        }
    }
}

// ---------------- bf16 helpers ----------------
__device__ __forceinline__ void mma_bf(float c[4], const unsigned a[4],
                                       unsigned b0, unsigned b1) {
    asm volatile(
        "mma.sync.aligned.m16n8k16.row.col.f32.bf16.bf16.f32 "
        "{%0,%1,%2,%3}, {%4,%5,%6,%7}, {%8,%9}, {%0,%1,%2,%3};"
        : "+f"(c[0]), "+f"(c[1]), "+f"(c[2]), "+f"(c[3])
        : "r"(a[0]), "r"(a[1]), "r"(a[2]), "r"(a[3]), "r"(b0), "r"(b1));
}
__device__ __forceinline__ unsigned pk2(float lo, float hi) {
    unsigned r;
    asm("cvt.rn.bf16x2.f32 %0, %1, %2;" : "=r"(r) : "f"(hi), "f"(lo));
    return r;
}
__device__ __forceinline__ void cp16(unsigned s, const void* g) {
    asm volatile("cp.async.cg.shared.global [%0], [%1], 16;" :: "r"(s), "l"(g) : "memory");
}
__device__ __forceinline__ unsigned smem_u32(const void* p) {
    unsigned a;
    asm("{ .reg .u64 t; cvta.to.shared.u64 t, %1; cvt.u32.u64 %0, t; }" : "=r"(a) : "l"(p));
    return a;
}

// ---------------- flash attention bf16: q-tile 128, 8 warps x 16 rows x 64 cols ----------------
#define KPW 36                 // words per row (64 bf16 + 8 pad = 144 B)
#define KPB 144
#define K0OFF 18432
#define V0OFF (18432 + 9216)
#define K1OFF (18432 + 2*9216)
#define V1OFF (18432 + 3*9216)
#define ATT_SMEM (18432 + 4*9216)   // 55296 B

__global__ __launch_bounds__(256, 2) void k_att() {
    extern __shared__ char smem[];
    unsigned sb = smem_u32(smem);
    __nv_bfloat16* Qb = (__nv_bfloat16*)smem;     // [128 q][72 bf16]
    const unsigned* SW = (const unsigned*)smem;   // word view

    int q0 = blockIdx.x * 128, head = blockIdx.y, n = blockIdx.z;
    int tid = threadIdx.x, warp = tid >> 5, lane = tid & 31;
    int tg = lane >> 2, tq = lane & 3;
    int r0 = warp * 16 + tg;

    const float* qp = g_qkv + ((size_t)n * 256 + head * 64) * HW;
    const __nv_bfloat16* kg = g_kbf + (size_t)n * HW * 256;                   // [pix][256]
    const __nv_bfloat16* vg = g_vbf + ((size_t)n * 256 + head * 64) * (size_t)HW;

    int cj = tid & 7, cd = tid >> 3;              // cd 0..31

    // prologue: K/V tile 0 into buffer 0
    {
        const __nv_bfloat16* ks = kg + (size_t)cd * 256 + head * 64 + cj * 8;
        cp16(sb + K0OFF + cd * KPB + cj * 16, ks);
        cp16(sb + K0OFF + (cd + 32) * KPB + cj * 16, ks + (size_t)32 * 256);
        const __nv_bfloat16* vs = vg + (size_t)cd * HW + cj * 8;
        cp16(sb + V0OFF + cd * KPB + cj * 16, vs);
        cp16(sb + V0OFF + (cd + 32) * KPB + cj * 16, vs + (size_t)32 * HW);
    }
    asm volatile("cp.async.commit_group;" ::: "memory");

    // stage Q (prescaled by 0.125) as bf16 [q][d]
    {
        int lx = tid & 31;
#pragma unroll
        for (int rr = 0; rr < 8; rr++) {
            int d = (tid >> 5) + rr * 8;
            float4 v = *(const float4*)&qp[(size_t)d * HW + q0 + lx * 4];
            Qb[(lx * 4 + 0) * 72 + d] = __float2bfloat16(v.x * 0.125f);
            Qb[(lx * 4 + 1) * 72 + d] = __float2bfloat16(v.y * 0.125f);
            Qb[(lx * 4 + 2) * 72 + d] = __float2bfloat16(v.z * 0.125f);
            Qb[(lx * 4 + 3) * 72 + d] = __float2bfloat16(v.w * 0.125f);
        }
    }
    __syncthreads();

    // resident Q A-fragments
    unsigned qa[4][4];
#pragma unroll
    for (int kf = 0; kf < 4; kf++) {
        qa[kf][0] = SW[r0 * KPW + kf * 8 + tq];
        qa[kf][1] = SW[(r0 + 8) * KPW + kf * 8 + tq];
        qa[kf][2] = SW[r0 * KPW + kf * 8 + tq + 4];
        qa[kf][3] = SW[(r0 + 8) * KPW + kf * 8 + tq + 4];
    }

    float o[8][4] = {};
    float m0 = -1e30f, m1 = -1e30f, l0 = 0.f, l1 = 0.f;

    for (int kt = 0; kt < 64; kt++) {
        asm volatile("cp.async.wait_group 0;" ::: "memory");
        __syncthreads();   // tile[cur] visible; everyone done with buf[nxt]
        int cur = kt & 1;
        if (kt < 63) {
            int kOf = cur ? K0OFF : K1OFF, vOf = cur ? V0OFF : V1OFF;
            const __nv_bfloat16* ks = kg + (size_t)((kt + 1) * 64 + cd) * 256 + head * 64 + cj * 8;
            cp16(sb + kOf + cd * KPB + cj * 16, ks);
            cp16(sb + kOf + (cd + 32) * KPB + cj * 16, ks + (size_t)32 * 256);
            const __nv_bfloat16* vs = vg + (size_t)cd * HW + (kt + 1) * 64 + cj * 8;
            cp16(sb + vOf + cd * KPB + cj * 16, vs);
            cp16(sb + vOf + (cd + 32) * KPB + cj * 16, vs + (size_t)32 * HW);
            asm volatile("cp.async.commit_group;" ::: "memory");
        }
        const unsigned* Kw = SW + (cur ? K1OFF : K0OFF) / 4;
        const unsigned* Vw = SW + (cur ? V1OFF : V0OFF) / 4;

        // ---- S = Q K^T
        float sf[8][4] = {};
#pragma unroll
        for (int nf = 0; nf < 8; nf++) {
            int ncol = nf * 8 + tg;
#pragma unroll
            for (int kf = 0; kf < 4; kf++) {
                unsigned b0 = Kw[ncol * KPW + kf * 8 + tq];
                unsigned b1 = Kw[ncol * KPW + kf * 8 + tq + 4];
                mma_bf(sf[nf], qa[kf], b0, b1);
            }
        }

        // ---- warp-local online softmax (rows r0, r0+8)
        float mx0 = -1e30f, mx1 = -1e30f;
#pragma unroll
        for (int nf = 0; nf < 8; nf++) {
            mx0 = fmaxf(mx0, fmaxf(sf[nf][0], sf[nf][1]));
            mx1 = fmaxf(mx1, fmaxf(sf[nf][2], sf[nf][3]));
        }
        mx0 = fmaxf(mx0, __shfl_xor_sync(0xffffffffu, mx0, 1));
        mx0 = fmaxf(mx0, __shfl_xor_sync(0xffffffffu, mx0, 2));
        mx1 = fmaxf(mx1, __shfl_xor_sync(0xffffffffu, mx1, 1));
        mx1 = fmaxf(mx1, __shfl_xor_sync(0xffffffffu, mx1, 2));
        float mn0 = fmaxf(m0, mx0), mn1 = fmaxf(m1, mx1);
        float al0 = __expf(m0 - mn0), al1 = __expf(m1 - mn1);
        m0 = mn0; m1 = mn1;
        float rs0 = 0.f, rs1 = 0.f;
#pragma unroll
        for (int nf = 0; nf < 8; nf++) {
            sf[nf][0] = __expf(sf[nf][0] - mn0);
            sf[nf][1] = __expf(sf[nf][1] - mn0);
            sf[nf][2] = __expf(sf[nf][2] - mn1);
            sf[nf][3] = __expf(sf[nf][3] - mn1);
            rs0 += sf[nf][0] + sf[nf][1];
            rs1 += sf[nf][2] + sf[nf][3];
        }
        rs0 += __shfl_xor_sync(0xffffffffu, rs0, 1);
        rs0 += __shfl_xor_sync(0xffffffffu, rs0, 2);
        rs1 += __shfl_xor_sync(0xffffffffu, rs1, 1);
        rs1 += __shfl_xor_sync(0xffffffffu, rs1, 2);
        l0 = l0 * al0 + rs0;
        l1 = l1 * al1 + rs1;
#pragma unroll
        for (int nf = 0; nf < 8; nf++) {
            o[nf][0] *= al0; o[nf][1] *= al0;
            o[nf][2] *= al1; o[nf][3] *= al1;
        }

        // ---- P fragments in registers (C-frag -> A-frag, FA2)
        unsigned pa[4][4];
#pragma unroll
        for (int kc = 0; kc < 4; kc++) {
            pa[kc][0] = pk2(sf[2*kc][0],   sf[2*kc][1]);
            pa[kc][1] = pk2(sf[2*kc][2],   sf[2*kc][3]);
            pa[kc][2] = pk2(sf[2*kc+1][0], sf[2*kc+1][1]);
            pa[kc][3] = pk2(sf[2*kc+1][2], sf[2*kc+1][3]);
        }

        // ---- O += P V
#pragma unroll
        for (int nf = 0; nf < 8; nf++) {
            int dcol = nf * 8 + tg;
#pragma unroll
            for (int kc = 0; kc < 4; kc++) {
                unsigned b0 = Vw[dcol * KPW + kc * 8 + tq];
                unsigned b1 = Vw[dcol * KPW + kc * 8 + tq + 4];
                mma_bf(o[nf], pa[kc], b0, b1);
            }
        }
    }

    float li0 = 1.f / l0, li1 = 1.f / l1;
    float* yb = g_y + ((size_t)n * C_CH + head * 64) * HW + q0;
#pragma unroll
    for (int nf = 0; nf < 8; nf++) {
        int dv = nf * 8 + 2 * tq;
        yb[(size_t)dv * HW + r0]           = o[nf][0] * li0;
        yb[(size_t)(dv + 1) * HW + r0]     = o[nf][1] * li0;
        yb[(size_t)dv * HW + r0 + 8]       = o[nf][2] * li1;
        yb[(size_t)(dv + 1) * HW + r0 + 8] = o[nf][3] * li1;
    }
}

// ---------------- out projection + bias + residual ----------------
__global__ __launch_bounds__(256) void k_out(const float* __restrict__ x,
                                             const float* __restrict__ w,
                                             const float* __restrict__ bias,
                                             float* __restrict__ out) {
    __shared__ float As[64][20];
    __shared__ float Bs[16][68];
    int n = blockIdx.z, o0 = blockIdx.y * 64, p0 = blockIdx.x * 64;
    int tid = threadIdx.x, tx = tid & 15, ty = tid >> 4;
    float acc[4][4] = {};
    int ar = tid >> 2, ac = (tid & 3) << 2;
    int br = tid >> 4, bc = (tid & 15) << 2;
    for (int k0 = 0; k0 < C_CH; k0 += 16) {
        *(float4*)&As[ar][ac] = *(const float4*)&w[(size_t)(o0 + ar) * C_CH + k0 + ac];
        *(float4*)&Bs[br][bc] =
            *(const float4*)&g_y[((size_t)n * C_CH + k0 + br) * HW + p0 + bc];
        __syncthreads();
#pragma unroll
        for (int kk = 0; kk < 16; kk++) {
            float av[4];
#pragma unroll
            for (int i = 0; i < 4; i++) av[i] = As[ty * 4 + i][kk];
            float4 b4 = *(const float4*)&Bs[kk][tx << 2];
            float bvv[4] = {b4.x, b4.y, b4.z, b4.w};
#pragma unroll
            for (int i = 0; i < 4; i++)
#pragma unroll
                for (int j = 0; j < 4; j++) acc[i][j] += av[i] * bvv[j];
        }
        __syncthreads();
    }
#pragma unroll
    for (int i = 0; i < 4; i++) {
        int o = o0 + ty * 4 + i;
        float bi = bias[o];
        size_t idx = ((size_t)n * C_CH + o) * HW + p0 + (tx << 2);
        float4 xr = *(const float4*)&x[idx];
        float4 r = make_float4(acc[i][0] + bi + xr.x, acc[i][1] + bi + xr.y,
                               acc[i][2] + bi + xr.z, acc[i][3] + bi + xr.w);
        *(float4*)&out[idx] = r;
    }
}

// ---------------- launch ----------------
extern "C" void kernel_launch(void* const* d_in, const int* in_sizes, int n_in,
                              void* d_out, int out_size) {
    (void)in_sizes; (void)n_in; (void)out_size;
    const float* x     = (const float*)d_in[0];
    const float* gamma = (const float*)d_in[1];
    const float* beta  = (const float*)d_in[2];
    const float* w_qkv = (const float*)d_in[3];
    const float* b_qkv = (const float*)d_in[4];
    const float* w_out = (const float*)d_in[5];
    const float* b_out = (const float*)d_in[6];
    float* out = (float*)d_out;

    cudaFuncSetAttribute(k_att, cudaFuncAttributeMaxDynamicSharedMemorySize, ATT_SMEM);

    k_stat1<<<dim3(128, N_B), 256>>>(x);
    k_stat2<<<N_B, 128>>>();
    k_qkv<<<dim3(HW / 64, 12, N_B), 256>>>(x, gamma, beta, w_qkv, b_qkv);
    k_att<<<dim3(HW / 128, NH, N_B), 256, ATT_SMEM>>>();
    k_out<<<dim3(HW / 64, 4, N_B), 256>>>(x, w_out, b_out, out);
}